// round 14
// baseline (speedup 1.0000x reference)
#include <cuda_runtime.h>
#include <cuda_bf16.h>
#include <math.h>
#include <stdint.h>

// Problem constants
#define BSZ 16
#define TT  500
#define EE  1024
#define VV  4000
#define LL  100
#define SS  201
#define GG  101
#define MM  (BSZ*TT)     // 8000
#define MPAD 8064        // 63*128
#define NPAD 4096        // 32*128
#define NEGF (-1e30f)
#define SELP 112
#define UNUSED_SENT 0x7fffffff

// GEMM tiling: 8 warps (2M x 4N), warp tile 64x32, BK=32 (best measured)
#define BM 128
#define BN 128
#define BK 32
#define NST 4
#define KITERS (EE/BK)   // 32
#define NTILES (NPAD/BN) // 32

// Scratch (device globals: allocation-free per harness rules)
__device__ __nv_bfloat16 g_hsb[(size_t)MPAD * EE];   // COMPACT rows; dead rows zero
__device__ __nv_bfloat16 g_Wtb[(size_t)NPAD * EE];
__device__ int g_colidx[(size_t)BSZ * VV];
__device__ int g_us[BSZ * GG];
__device__ int g_base[BSZ + 1];
__device__ int g_live;
__device__ int g_rowsrc[MPAD];
__device__ int g_rowb[MPAD];
__device__ float2 g_part[(size_t)MM * NTILES];
__device__ float g_sel[(size_t)MM * SELP];
__device__ float g_ll[BSZ];

// ---------------------------------------------------------------------------
__device__ __forceinline__ uint32_t smem_u32(const void* p) {
    uint32_t a;
    asm("{ .reg .u64 t; cvta.to.shared.u64 t, %1; cvt.u32.u64 %0, t; }" : "=r"(a) : "l"(p));
    return a;
}
__device__ __forceinline__ void cp16(uint32_t dst, const void* src) {
    asm volatile("cp.async.cg.shared.global [%0], [%1], 16;" :: "r"(dst), "l"(src));
}
// 64-byte-row swizzle: (row, 16B-chunk c), c in 0..3
__device__ __forceinline__ uint32_t swz(int row, int c) {
    return (uint32_t)(row * 64 + ((c ^ ((row >> 1) & 3)) << 4));
}

// ---------------------------------------------------------------------------
// Merged setup + W conversion.
// Blocks 0..16: setup (prefix/rowmap/colmap). Blocks 17+: W transpose+convert.
// ---------------------------------------------------------------------------
__global__ __launch_bounds__(256)
void setup_convW_kernel(const int* __restrict__ ilens, const int* __restrict__ ys,
                        const float* __restrict__ W) {
    const int tid = threadIdx.x;
    if (blockIdx.x == 0) {
        if (tid == 0) {
            int acc = 0;
            for (int b = 0; b < BSZ; b++) { g_base[b] = acc; acc += ilens[b]; }
            g_base[BSZ] = acc;
            g_live = acc;
        }
        __syncthreads();
        for (int i = tid; i < MPAD; i += 256) { g_rowsrc[i] = -1; g_rowb[i] = -1; }
        __syncthreads();
        for (int row = tid; row < MM; row += 256) {
            int b = row / TT, t = row % TT;
            if (t < ilens[b]) {
                int o = g_base[b] + t;
                g_rowsrc[o] = row;
                g_rowb[o] = b;
            }
        }
    } else if (blockIdx.x <= BSZ) {
        const int b = blockIdx.x - 1;
        for (int i = tid; i < VV; i += 256)
            g_colidx[(size_t)b * VV + i] = UNUSED_SENT;
        __syncthreads();
        int col = 0;
        if (tid < GG) {
            if (tid > 0) {
                int y = ys[b * LL + tid - 1];
                col = y < 0 ? 0 : y;
            }
            atomicMin(&g_colidx[(size_t)b * VV + col], tid);
        }
        __syncthreads();
        if (tid < GG)
            g_us[b * GG + tid] = g_colidx[(size_t)b * VV + col];
    } else {
        __shared__ float t[32][33];
        int wb = blockIdx.x - (BSZ + 1);
        int n0 = (wb & 127) * 32;        // 128 n-tiles
        int k0 = (wb >> 7) * 32;         // 32 k-tiles
        int tx = tid & 31;
        int ty = tid >> 5;
        if (n0 >= VV) {
#pragma unroll
            for (int j = 0; j < 32; j += 8)
                g_Wtb[(size_t)(n0 + ty + j) * EE + k0 + tx] = __float2bfloat16(0.f);
            return;
        }
#pragma unroll
        for (int j = 0; j < 32; j += 8)
            t[ty + j][tx] = W[(size_t)(k0 + ty + j) * VV + n0 + tx];
        __syncthreads();
#pragma unroll
        for (int j = 0; j < 32; j += 8)
            g_Wtb[(size_t)(n0 + ty + j) * EE + k0 + tx] = __float2bfloat16(t[tx][ty + j]);
    }
}

// ---------------------------------------------------------------------------
__global__ __launch_bounds__(256)
void conv_hs_kernel(const float* __restrict__ hs) {
    size_t i = ((size_t)blockIdx.x * 256 + threadIdx.x) * 4;
    if (i >= (size_t)MPAD * EE) return;
    int orow = (int)(i >> 10);
    int k = (int)(i & 1023);
    int src = g_rowsrc[orow];
    float4 v = make_float4(0.f, 0.f, 0.f, 0.f);
    if (src >= 0) v = *(const float4*)(hs + (size_t)src * EE + k);
    __nv_bfloat162* dst = (__nv_bfloat162*)(g_hsb + i);
    dst[0] = __nv_bfloat162(__float2bfloat16(v.x), __float2bfloat16(v.y));
    dst[1] = __nv_bfloat162(__float2bfloat16(v.z), __float2bfloat16(v.w));
}

// ---------------------------------------------------------------------------
// Main GEMM: 256 threads, 8 warps (2Mx4N), warp tile 64x32, BK=32/NST=4
// (R10 best-measured mainloop), fused LSE + selected-logit scatter.
// ---------------------------------------------------------------------------
__global__ __launch_bounds__(256, 2)
void gemm_lse_kernel(const float* __restrict__ bias) {
    const int by = blockIdx.y;
    const int row0 = by * BM;
    if (row0 >= g_live) return;

    extern __shared__ char dsm[];
    __shared__ float2 red[4][BM];
    __shared__ int scol[2][BM];

    const int tid = threadIdx.x;
    const int warp = tid >> 5, lane = tid & 31;
    const int wm = (warp & 1) * 64, wn = (warp >> 1) * 32;
    const int bx = blockIdx.x;
    const int col0 = bx * BN;
    const uint32_t sbase = smem_u32(dsm);

    // per-thread cp.async assignment: row = tid/2, two 16B chunks
    const int lrow = tid >> 1;
    const int lc0 = (tid & 1) * 2;
    const uint32_t dA0 = swz(lrow, lc0);
    const uint32_t dA1 = swz(lrow, lc0 + 1);
    const __nv_bfloat16* srcA = g_hsb + ((size_t)row0 + lrow) * EE + lc0 * 8;
    const __nv_bfloat16* srcB = g_Wtb + ((size_t)col0 + lrow) * EE + lc0 * 8;

    // Stage per-batch column maps for this tile's rows (<=2 batches).
    const int b_lo = g_rowb[row0];
    const int lastrow = (row0 + BM - 1 < g_live) ? row0 + BM - 1 : g_live - 1;
    const int b_hi = g_rowb[lastrow];
    if (tid < BM) {
        int gc = col0 + tid;
        bool okc = gc < VV;
        scol[0][tid] = okc ? g_colidx[(size_t)b_lo * VV + gc] : UNUSED_SENT;
        scol[1][tid] = (okc && b_hi >= 0) ? g_colidx[(size_t)b_hi * VV + gc] : UNUSED_SENT;
    }

    float acc[4][4][4];
#pragma unroll
    for (int mi = 0; mi < 4; mi++)
#pragma unroll
        for (int ni = 0; ni < 4; ni++)
#pragma unroll
            for (int r = 0; r < 4; r++) acc[mi][ni][r] = 0.f;

    uint32_t aoff[2][4], boff[2][4];
#pragma unroll
    for (int kk = 0; kk < 2; kk++) {
#pragma unroll
        for (int mi = 0; mi < 4; mi++) {
            int r = wm + mi * 16 + (lane & 15);
            int c = kk * 2 + ((lane >> 4) & 1);
            aoff[kk][mi] = sbase + swz(r, c);
        }
#pragma unroll
        for (int ni = 0; ni < 4; ni++) {
            int r = wn + ni * 8 + (lane & 7);
            int c = kk * 2 + ((lane >> 3) & 1);
            boff[kk][ni] = sbase + 8192 + swz(r, c);
        }
    }

#define LOAD_STAGE(st, kt) do { \
    uint32_t b_ = (uint32_t)(st) * 16384; \
    const __nv_bfloat16* a_ = srcA + (kt) * BK; \
    const __nv_bfloat16* w_ = srcB + (kt) * BK; \
    cp16(sbase + b_ + dA0, a_); \
    cp16(sbase + b_ + dA1, a_ + 8); \
    cp16(sbase + b_ + 8192 + dA0, w_); \
    cp16(sbase + b_ + 8192 + dA1, w_ + 8); \
    asm volatile("cp.async.commit_group;" ::: "memory"); \
} while (0)

    LOAD_STAGE(0, 0);
    LOAD_STAGE(1, 1);
    LOAD_STAGE(2, 2);

    for (int kt = 0; kt < KITERS; kt++) {
        const int st = kt & 3;
        if (kt < KITERS - 2)
            asm volatile("cp.async.wait_group 2;" ::: "memory");
        else if (kt == KITERS - 2)
            asm volatile("cp.async.wait_group 1;" ::: "memory");
        else
            asm volatile("cp.async.wait_group 0;" ::: "memory");
        __syncthreads();

        const uint32_t stb = (uint32_t)st * 16384;
#pragma unroll
        for (int kk = 0; kk < 2; kk++) {
            uint32_t af[4][4], bf[4][2];
#pragma unroll
            for (int mi = 0; mi < 4; mi++)
                asm volatile("ldmatrix.sync.aligned.m8n8.x4.shared.b16 {%0,%1,%2,%3}, [%4];"
                             : "=r"(af[mi][0]), "=r"(af[mi][1]), "=r"(af[mi][2]), "=r"(af[mi][3])
                             : "r"(aoff[kk][mi] + stb));
#pragma unroll
            for (int ni = 0; ni < 4; ni++)
                asm volatile("ldmatrix.sync.aligned.m8n8.x2.shared.b16 {%0,%1}, [%2];"
                             : "=r"(bf[ni][0]), "=r"(bf[ni][1])
                             : "r"(boff[kk][ni] + stb));
#pragma unroll
            for (int mi = 0; mi < 4; mi++)
#pragma unroll
                for (int ni = 0; ni < 4; ni++)
                    asm volatile(
                        "mma.sync.aligned.m16n8k16.row.col.f32.bf16.bf16.f32 "
                        "{%0,%1,%2,%3}, {%4,%5,%6,%7}, {%8,%9}, {%0,%1,%2,%3};"
                        : "+f"(acc[mi][ni][0]), "+f"(acc[mi][ni][1]),
                          "+f"(acc[mi][ni][2]), "+f"(acc[mi][ni][3])
                        : "r"(af[mi][0]), "r"(af[mi][1]), "r"(af[mi][2]), "r"(af[mi][3]),
                          "r"(bf[ni][0]), "r"(bf[ni][1]));
        }
        if (kt + 3 < KITERS) LOAD_STAGE((kt + 3) & 3, kt + 3);
    }
#undef LOAD_STAGE

    // Epilogue: bias add, scatter via smem map, LSE partials (max then sum)
#pragma unroll
    for (int mi = 0; mi < 4; mi++) {
        const int r1 = row0 + wm + mi * 16 + (lane >> 2);
        const int r2 = r1 + 8;
        const int b1 = g_rowb[r1];
        const int b2 = g_rowb[r2];
        const int* c1 = (b1 == b_lo) ? scol[0] : scol[1];
        const int* c2 = (b2 == b_lo) ? scol[0] : scol[1];
        float vv1[8], vv2[8];
#pragma unroll
        for (int ni = 0; ni < 4; ni++) {
            int lc = wn + ni * 8 + 2 * (lane & 3);
            int gcol = col0 + lc;
            bool ok = gcol < VV;
            float b0 = 0.f, bb = 0.f;
            if (ok) { float2 bv = *(const float2*)(bias + gcol); b0 = bv.x; bb = bv.y; }
            float a0 = acc[mi][ni][0] + b0, a1 = acc[mi][ni][1] + bb;
            float a2 = acc[mi][ni][2] + b0, a3 = acc[mi][ni][3] + bb;
            vv1[2 * ni] = ok ? a0 : NEGF; vv1[2 * ni + 1] = ok ? a1 : NEGF;
            vv2[2 * ni] = ok ? a2 : NEGF; vv2[2 * ni + 1] = ok ? a3 : NEGF;
            if (b1 >= 0) {
                int u0 = c1[lc], u1 = c1[lc + 1];
                if (u0 < GG) g_sel[(size_t)r1 * SELP + u0] = a0;
                if (u1 < GG) g_sel[(size_t)r1 * SELP + u1] = a1;
            }
            if (b2 >= 0) {
                int u0 = c2[lc], u1 = c2[lc + 1];
                if (u0 < GG) g_sel[(size_t)r2 * SELP + u0] = a2;
                if (u1 < GG) g_sel[(size_t)r2 * SELP + u1] = a3;
            }
        }
        float m1 = vv1[0], m2 = vv2[0];
#pragma unroll
        for (int j = 1; j < 8; j++) { m1 = fmaxf(m1, vv1[j]); m2 = fmaxf(m2, vv2[j]); }
        float s1 = 0.f, s2 = 0.f;
#pragma unroll
        for (int j = 0; j < 8; j++) { s1 += __expf(vv1[j] - m1); s2 += __expf(vv2[j] - m2); }

#pragma unroll
        for (int msk = 1; msk <= 2; msk <<= 1) {
            float om = __shfl_xor_sync(0xffffffffu, m1, msk);
            float os = __shfl_xor_sync(0xffffffffu, s1, msk);
            float M = fmaxf(m1, om);
            s1 = s1 * __expf(m1 - M) + os * __expf(om - M);
            m1 = M;
            om = __shfl_xor_sync(0xffffffffu, m2, msk);
            os = __shfl_xor_sync(0xffffffffu, s2, msk);
            M = fmaxf(m2, om);
            s2 = s2 * __expf(m2 - M) + os * __expf(om - M);
            m2 = M;
        }
        if ((lane & 3) == 0) {
            int rr = wm + mi * 16 + (lane >> 2);
            red[warp >> 1][rr] = make_float2(m1, s1);
            red[warp >> 1][rr + 8] = make_float2(m2, s2);
        }
    }
    __syncthreads();
    if (tid < BM) {
        float m = NEGF, s = 0.f;
#pragma unroll
        for (int j = 0; j < 4; j++) {
            float2 p = red[j][tid];
            float M = fmaxf(m, p.x);
            s = s * __expf(m - M) + p.y * __expf(p.x - M);
            m = M;
        }
        int grow = row0 + tid;
        if (grow < MM) g_part[(size_t)grow * NTILES + bx] = make_float2(m, s);
    }
}

// ---------------------------------------------------------------------------
// CTC DP (fused combine): per batch block computes lse per row, builds lps
// in shared directly from g_sel, then runs the forward DP.
// ---------------------------------------------------------------------------
__global__ __launch_bounds__(256)
void ctc_dp_kernel(const int* __restrict__ ys, const int* __restrict__ ilens,
                   const int* __restrict__ olens) {
    extern __shared__ float sm[];
    float* lps = sm;                     // [TT][GG]
    float* lse_s = sm + TT * GG;         // [TT]
    float* abuf = lse_s + TT;            // [2][256]
    __shared__ int us_s[GG];

    const int b = blockIdx.x;
    const int tid = threadIdx.x;
    const int wid = tid >> 5, lane = tid & 31;
    const int s = tid;
    const int ilen = ilens[b];
    const int base = g_base[b];

    if (tid < GG) us_s[tid] = g_us[b * GG + tid];

    // Per-row LSE reduce: warp w handles rows w, w+8, ...
    for (int t = wid; t < ilen; t += 8) {
        float2 p = g_part[(size_t)(base + t) * NTILES + lane];
        float m = p.x, sv = p.y;
#pragma unroll
        for (int msk = 16; msk > 0; msk >>= 1) {
            float om = __shfl_xor_sync(0xffffffffu, m, msk);
            float os = __shfl_xor_sync(0xffffffffu, sv, msk);
            float M = fmaxf(m, om);
            sv = sv * __expf(m - M) + os * __expf(om - M);
            m = M;
        }
        if (lane == 0) lse_s[t] = m + logf(sv);
    }
    __syncthreads();

    // Build lps[t][s] = sel[base+t][us[s]] - lse[t]
    for (int t = wid; t < ilen; t += 8) {
        const float* selrow = g_sel + (size_t)(base + t) * SELP;
        float lse = lse_s[t];
        for (int ss = lane; ss < GG; ss += 32)
            lps[t * GG + ss] = selrow[us_s[ss]] - lse;
    }

    // Per-state metadata
    int g = 0;
    bool allow = false;
    if (s < SS && (s & 1)) {
        int l = s >> 1;
        g = 1 + l;
        int yr = ys[b * LL + l];
        int y = yr < 0 ? 0 : yr;
        int ypr = -1;
        if (l > 0) {
            int yp = ys[b * LL + l - 1];
            ypr = yp < 0 ? 0 : yp;
        }
        allow = (y != 0) && (y != ypr);
    }
    __syncthreads();

    float* a0 = abuf;
    float* a1 = abuf + 256;
    a0[s] = (s == 0) ? lps[0] : ((s == 1) ? lps[1] : NEGF);
    __syncthreads();

    for (int t = 1; t < ilen; t++) {
        if (s < SS) {
            float v1 = a0[s];
            float v2 = (s >= 1) ? a0[s - 1] : NEGF;
            float v3 = (s >= 2 && allow) ? a0[s - 2] : NEGF;
            float m = fmaxf(v1, fmaxf(v2, v3));
            float sum = __expf(v1 - m) + __expf(v2 - m) + __expf(v3 - m);
            a1[s] = m + __logf(sum) + lps[t * GG + g];
        }
        __syncthreads();
        float* tmp = a0; a0 = a1; a1 = tmp;
    }

    if (tid == 0) {
        const int olen = olens[b];
        float va = a0[2 * olen];
        float vb = a0[2 * olen - 1];
        float m = fmaxf(va, vb);
        g_ll[b] = m + logf(expf(va - m) + expf(vb - m));
    }
}

__global__ void finalize_kernel(float* __restrict__ out) {
    if (threadIdx.x == 0) {
        float sum = 0.0f;
        for (int i = 0; i < BSZ; i++) sum += g_ll[i];
        out[0] = -sum / (float)BSZ;
    }
}

// ---------------------------------------------------------------------------
extern "C" void kernel_launch(void* const* d_in, const int* in_sizes, int n_in,
                              void* d_out, int out_size) {
    const float* hs    = (const float*)d_in[0];
    const float* W     = (const float*)d_in[1];
    const float* bias  = (const float*)d_in[2];
    const int*   ys    = (const int*)d_in[3];
    const int*   ilens = (const int*)d_in[4];
    const int*   olens = (const int*)d_in[5];
    float* out = (float*)d_out;

    // launch 1: setup + W convert (merged)
    setup_convW_kernel<<<1 + BSZ + (NPAD / 32) * (EE / 32), 256>>>(ilens, ys, W);
    // launch 2: hs convert (needs row map)
    conv_hs_kernel<<<(MPAD * EE) / 1024, 256>>>(hs);

    // launch 3: GEMM
    const int gemm_smem = NST * 16384;   // 64 KB
    cudaFuncSetAttribute(gemm_lse_kernel,
                         cudaFuncAttributeMaxDynamicSharedMemorySize, gemm_smem);
    dim3 ggrid(NPAD / BN, MPAD / BM);    // 32 x 63
    gemm_lse_kernel<<<ggrid, 256, gemm_smem>>>(bias);

    // launch 4: fused DP (profiled)
    const int dp_smem = (TT * GG + TT + 2 * 256) * sizeof(float);
    cudaFuncSetAttribute(ctc_dp_kernel,
                         cudaFuncAttributeMaxDynamicSharedMemorySize, dp_smem);
    ctc_dp_kernel<<<BSZ, 256, dp_smem>>>(ys, ilens, olens);

    // launch 5: finalize
    finalize_kernel<<<1, 32>>>(out);
}

// round 15
// speedup vs baseline: 1.3582x; 1.3582x over previous
#include <cuda_runtime.h>
#include <cuda_bf16.h>
#include <math.h>
#include <stdint.h>

// Problem constants
#define BSZ 16
#define TT  500
#define EE  1024
#define VV  4000
#define LL  100
#define SS  201
#define GG  101
#define MM  (BSZ*TT)     // 8000
#define MPAD 8064        // 63*128
#define NPAD 4096        // 32*128
#define NEGF (-1e30f)
#define SELP 112
#define UNUSED_SENT 0x7fffffff

// GEMM tiling: 8 warps (2M x 4N), warp tile 64x32, BK=32/NST=4 (best measured)
#define BM 128
#define BN 128
#define BK 32
#define NST 4
#define KITERS (EE/BK)   // 32
#define NTILES (NPAD/BN) // 32

// Scratch (device globals: allocation-free per harness rules)
__device__ __nv_bfloat16 g_hsb[(size_t)MPAD * EE];   // COMPACT rows; dead rows zero
__device__ __nv_bfloat16 g_Wtb[(size_t)NPAD * EE];
__device__ int g_colidx[(size_t)BSZ * VV];
__device__ int g_us[BSZ * GG];
__device__ int g_base[BSZ + 1];
__device__ int g_live;
__device__ int g_rowsrc[MPAD];
__device__ int g_rowb[MPAD];
__device__ float2 g_part[(size_t)MM * NTILES];
__device__ float g_sel[(size_t)MM * SELP];
__device__ float g_p[(size_t)MM * GG];               // probabilities exp(lp), compact rows
__device__ float g_ll[BSZ];

// ---------------------------------------------------------------------------
__device__ __forceinline__ uint32_t smem_u32(const void* p) {
    uint32_t a;
    asm("{ .reg .u64 t; cvta.to.shared.u64 t, %1; cvt.u32.u64 %0, t; }" : "=r"(a) : "l"(p));
    return a;
}
__device__ __forceinline__ void cp16(uint32_t dst, const void* src) {
    asm volatile("cp.async.cg.shared.global [%0], [%1], 16;" :: "r"(dst), "l"(src));
}
// 64-byte-row swizzle: (row, 16B-chunk c), c in 0..3
__device__ __forceinline__ uint32_t swz(int row, int c) {
    return (uint32_t)(row * 64 + ((c ^ ((row >> 1) & 3)) << 4));
}

// ---------------------------------------------------------------------------
// Merged setup + W conversion.
// ---------------------------------------------------------------------------
__global__ __launch_bounds__(256)
void setup_convW_kernel(const int* __restrict__ ilens, const int* __restrict__ ys,
                        const float* __restrict__ W) {
    const int tid = threadIdx.x;
    if (blockIdx.x == 0) {
        if (tid == 0) {
            int acc = 0;
            for (int b = 0; b < BSZ; b++) { g_base[b] = acc; acc += ilens[b]; }
            g_base[BSZ] = acc;
            g_live = acc;
        }
        __syncthreads();
        for (int i = tid; i < MPAD; i += 256) { g_rowsrc[i] = -1; g_rowb[i] = -1; }
        __syncthreads();
        for (int row = tid; row < MM; row += 256) {
            int b = row / TT, t = row % TT;
            if (t < ilens[b]) {
                int o = g_base[b] + t;
                g_rowsrc[o] = row;
                g_rowb[o] = b;
            }
        }
    } else if (blockIdx.x <= BSZ) {
        const int b = blockIdx.x - 1;
        for (int i = tid; i < VV; i += 256)
            g_colidx[(size_t)b * VV + i] = UNUSED_SENT;
        __syncthreads();
        int col = 0;
        if (tid < GG) {
            if (tid > 0) {
                int y = ys[b * LL + tid - 1];
                col = y < 0 ? 0 : y;
            }
            atomicMin(&g_colidx[(size_t)b * VV + col], tid);
        }
        __syncthreads();
        if (tid < GG)
            g_us[b * GG + tid] = g_colidx[(size_t)b * VV + col];
    } else {
        __shared__ float t[32][33];
        int wb = blockIdx.x - (BSZ + 1);
        int n0 = (wb & 127) * 32;
        int k0 = (wb >> 7) * 32;
        int tx = tid & 31;
        int ty = tid >> 5;
        if (n0 >= VV) {
#pragma unroll
            for (int j = 0; j < 32; j += 8)
                g_Wtb[(size_t)(n0 + ty + j) * EE + k0 + tx] = __float2bfloat16(0.f);
            return;
        }
#pragma unroll
        for (int j = 0; j < 32; j += 8)
            t[ty + j][tx] = W[(size_t)(k0 + ty + j) * VV + n0 + tx];
        __syncthreads();
#pragma unroll
        for (int j = 0; j < 32; j += 8)
            g_Wtb[(size_t)(n0 + ty + j) * EE + k0 + tx] = __float2bfloat16(t[tx][ty + j]);
    }
}

// ---------------------------------------------------------------------------
__global__ __launch_bounds__(256)
void conv_hs_kernel(const float* __restrict__ hs) {
    size_t i = ((size_t)blockIdx.x * 256 + threadIdx.x) * 4;
    if (i >= (size_t)MPAD * EE) return;
    int orow = (int)(i >> 10);
    int k = (int)(i & 1023);
    int src = g_rowsrc[orow];
    float4 v = make_float4(0.f, 0.f, 0.f, 0.f);
    if (src >= 0) v = *(const float4*)(hs + (size_t)src * EE + k);
    __nv_bfloat162* dst = (__nv_bfloat162*)(g_hsb + i);
    dst[0] = __nv_bfloat162(__float2bfloat16(v.x), __float2bfloat16(v.y));
    dst[1] = __nv_bfloat162(__float2bfloat16(v.z), __float2bfloat16(v.w));
}

// ---------------------------------------------------------------------------
// Main GEMM (R10 best-measured mainloop), fused LSE + selected-logit scatter.
// ---------------------------------------------------------------------------
__global__ __launch_bounds__(256, 2)
void gemm_lse_kernel(const float* __restrict__ bias) {
    const int by = blockIdx.y;
    const int row0 = by * BM;
    if (row0 >= g_live) return;

    extern __shared__ char dsm[];
    __shared__ float2 red[4][BM];
    __shared__ int scol[2][BM];

    const int tid = threadIdx.x;
    const int warp = tid >> 5, lane = tid & 31;
    const int wm = (warp & 1) * 64, wn = (warp >> 1) * 32;
    const int bx = blockIdx.x;
    const int col0 = bx * BN;
    const uint32_t sbase = smem_u32(dsm);

    const int lrow = tid >> 1;
    const int lc0 = (tid & 1) * 2;
    const uint32_t dA0 = swz(lrow, lc0);
    const uint32_t dA1 = swz(lrow, lc0 + 1);
    const __nv_bfloat16* srcA = g_hsb + ((size_t)row0 + lrow) * EE + lc0 * 8;
    const __nv_bfloat16* srcB = g_Wtb + ((size_t)col0 + lrow) * EE + lc0 * 8;

    const int b_lo = g_rowb[row0];
    const int lastrow = (row0 + BM - 1 < g_live) ? row0 + BM - 1 : g_live - 1;
    const int b_hi = g_rowb[lastrow];
    if (tid < BM) {
        int gc = col0 + tid;
        bool okc = gc < VV;
        scol[0][tid] = okc ? g_colidx[(size_t)b_lo * VV + gc] : UNUSED_SENT;
        scol[1][tid] = (okc && b_hi >= 0) ? g_colidx[(size_t)b_hi * VV + gc] : UNUSED_SENT;
    }

    float acc[4][4][4];
#pragma unroll
    for (int mi = 0; mi < 4; mi++)
#pragma unroll
        for (int ni = 0; ni < 4; ni++)
#pragma unroll
            for (int r = 0; r < 4; r++) acc[mi][ni][r] = 0.f;

    uint32_t aoff[2][4], boff[2][4];
#pragma unroll
    for (int kk = 0; kk < 2; kk++) {
#pragma unroll
        for (int mi = 0; mi < 4; mi++) {
            int r = wm + mi * 16 + (lane & 15);
            int c = kk * 2 + ((lane >> 4) & 1);
            aoff[kk][mi] = sbase + swz(r, c);
        }
#pragma unroll
        for (int ni = 0; ni < 4; ni++) {
            int r = wn + ni * 8 + (lane & 7);
            int c = kk * 2 + ((lane >> 3) & 1);
            boff[kk][ni] = sbase + 8192 + swz(r, c);
        }
    }

#define LOAD_STAGE(st, kt) do { \
    uint32_t b_ = (uint32_t)(st) * 16384; \
    const __nv_bfloat16* a_ = srcA + (kt) * BK; \
    const __nv_bfloat16* w_ = srcB + (kt) * BK; \
    cp16(sbase + b_ + dA0, a_); \
    cp16(sbase + b_ + dA1, a_ + 8); \
    cp16(sbase + b_ + 8192 + dA0, w_); \
    cp16(sbase + b_ + 8192 + dA1, w_ + 8); \
    asm volatile("cp.async.commit_group;" ::: "memory"); \
} while (0)

    LOAD_STAGE(0, 0);
    LOAD_STAGE(1, 1);
    LOAD_STAGE(2, 2);

    for (int kt = 0; kt < KITERS; kt++) {
        const int st = kt & 3;
        if (kt < KITERS - 2)
            asm volatile("cp.async.wait_group 2;" ::: "memory");
        else if (kt == KITERS - 2)
            asm volatile("cp.async.wait_group 1;" ::: "memory");
        else
            asm volatile("cp.async.wait_group 0;" ::: "memory");
        __syncthreads();

        const uint32_t stb = (uint32_t)st * 16384;
#pragma unroll
        for (int kk = 0; kk < 2; kk++) {
            uint32_t af[4][4], bf[4][2];
#pragma unroll
            for (int mi = 0; mi < 4; mi++)
                asm volatile("ldmatrix.sync.aligned.m8n8.x4.shared.b16 {%0,%1,%2,%3}, [%4];"
                             : "=r"(af[mi][0]), "=r"(af[mi][1]), "=r"(af[mi][2]), "=r"(af[mi][3])
                             : "r"(aoff[kk][mi] + stb));
#pragma unroll
            for (int ni = 0; ni < 4; ni++)
                asm volatile("ldmatrix.sync.aligned.m8n8.x2.shared.b16 {%0,%1}, [%2];"
                             : "=r"(bf[ni][0]), "=r"(bf[ni][1])
                             : "r"(boff[kk][ni] + stb));
#pragma unroll
            for (int mi = 0; mi < 4; mi++)
#pragma unroll
                for (int ni = 0; ni < 4; ni++)
                    asm volatile(
                        "mma.sync.aligned.m16n8k16.row.col.f32.bf16.bf16.f32 "
                        "{%0,%1,%2,%3}, {%4,%5,%6,%7}, {%8,%9}, {%0,%1,%2,%3};"
                        : "+f"(acc[mi][ni][0]), "+f"(acc[mi][ni][1]),
                          "+f"(acc[mi][ni][2]), "+f"(acc[mi][ni][3])
                        : "r"(af[mi][0]), "r"(af[mi][1]), "r"(af[mi][2]), "r"(af[mi][3]),
                          "r"(bf[ni][0]), "r"(bf[ni][1]));
        }
        if (kt + 3 < KITERS) LOAD_STAGE((kt + 3) & 3, kt + 3);
    }
#undef LOAD_STAGE

    // Epilogue: bias add, scatter via smem map, LSE partials (max then sum)
#pragma unroll
    for (int mi = 0; mi < 4; mi++) {
        const int r1 = row0 + wm + mi * 16 + (lane >> 2);
        const int r2 = r1 + 8;
        const int b1 = g_rowb[r1];
        const int b2 = g_rowb[r2];
        const int* c1 = (b1 == b_lo) ? scol[0] : scol[1];
        const int* c2 = (b2 == b_lo) ? scol[0] : scol[1];
        float vv1[8], vv2[8];
#pragma unroll
        for (int ni = 0; ni < 4; ni++) {
            int lc = wn + ni * 8 + 2 * (lane & 3);
            int gcol = col0 + lc;
            bool ok = gcol < VV;
            float b0 = 0.f, bb = 0.f;
            if (ok) { float2 bv = *(const float2*)(bias + gcol); b0 = bv.x; bb = bv.y; }
            float a0 = acc[mi][ni][0] + b0, a1 = acc[mi][ni][1] + bb;
            float a2 = acc[mi][ni][2] + b0, a3 = acc[mi][ni][3] + bb;
            vv1[2 * ni] = ok ? a0 : NEGF; vv1[2 * ni + 1] = ok ? a1 : NEGF;
            vv2[2 * ni] = ok ? a2 : NEGF; vv2[2 * ni + 1] = ok ? a3 : NEGF;
            if (b1 >= 0) {
                int u0 = c1[lc], u1 = c1[lc + 1];
                if (u0 < GG) g_sel[(size_t)r1 * SELP + u0] = a0;
                if (u1 < GG) g_sel[(size_t)r1 * SELP + u1] = a1;
            }
            if (b2 >= 0) {
                int u0 = c2[lc], u1 = c2[lc + 1];
                if (u0 < GG) g_sel[(size_t)r2 * SELP + u0] = a2;
                if (u1 < GG) g_sel[(size_t)r2 * SELP + u1] = a3;
            }
        }
        float m1 = vv1[0], m2 = vv2[0];
#pragma unroll
        for (int j = 1; j < 8; j++) { m1 = fmaxf(m1, vv1[j]); m2 = fmaxf(m2, vv2[j]); }
        float s1 = 0.f, s2 = 0.f;
#pragma unroll
        for (int j = 0; j < 8; j++) { s1 += __expf(vv1[j] - m1); s2 += __expf(vv2[j] - m2); }

#pragma unroll
        for (int msk = 1; msk <= 2; msk <<= 1) {
            float om = __shfl_xor_sync(0xffffffffu, m1, msk);
            float os = __shfl_xor_sync(0xffffffffu, s1, msk);
            float M = fmaxf(m1, om);
            s1 = s1 * __expf(m1 - M) + os * __expf(om - M);
            m1 = M;
            om = __shfl_xor_sync(0xffffffffu, m2, msk);
            os = __shfl_xor_sync(0xffffffffu, s2, msk);
            M = fmaxf(m2, om);
            s2 = s2 * __expf(m2 - M) + os * __expf(om - M);
            m2 = M;
        }
        if ((lane & 3) == 0) {
            int rr = wm + mi * 16 + (lane >> 2);
            red[warp >> 1][rr] = make_float2(m1, s1);
            red[warp >> 1][rr + 8] = make_float2(m2, s2);
        }
    }
    __syncthreads();
    if (tid < BM) {
        float m = NEGF, s = 0.f;
#pragma unroll
        for (int j = 0; j < 4; j++) {
            float2 p = red[j][tid];
            float M = fmaxf(m, p.x);
            s = s * __expf(m - M) + p.y * __expf(p.x - M);
            m = M;
        }
        int grow = row0 + tid;
        if (grow < MM) g_part[(size_t)grow * NTILES + bx] = make_float2(m, s);
    }
}

// ---------------------------------------------------------------------------
// Combine (8000 blocks): lse reduce + p[o][s] = exp(sel[o][us[s]] - lse)
// ---------------------------------------------------------------------------
__global__ __launch_bounds__(128)
void combine_kernel() {
    const int o = blockIdx.x;
    const int b = g_rowb[o];
    if (b < 0) return;

    __shared__ float s_lse;
    const int tid = threadIdx.x;
    if (tid < 32) {
        float2 p = g_part[(size_t)o * NTILES + tid];
        float m = p.x, s = p.y;
#pragma unroll
        for (int msk = 16; msk > 0; msk >>= 1) {
            float om = __shfl_xor_sync(0xffffffffu, m, msk);
            float os = __shfl_xor_sync(0xffffffffu, s, msk);
            float M = fmaxf(m, om);
            s = s * __expf(m - M) + os * __expf(om - M);
            m = M;
        }
        if (tid == 0) s_lse = m + logf(s);
    }
    __syncthreads();
    if (tid >= GG) return;
    int u = g_us[b * GG + tid];
    g_p[(size_t)o * GG + tid] = __expf(g_sel[(size_t)o * SELP + u] - s_lse);
}

// ---------------------------------------------------------------------------
// CTC forward DP in LINEAR domain with periodic rescaling.
// One block per batch element; p staged in shared.
// ---------------------------------------------------------------------------
__global__ __launch_bounds__(256)
void ctc_dp_kernel(const int* __restrict__ ys, const int* __restrict__ ilens,
                   const int* __restrict__ olens) {
    extern __shared__ float sm[];
    float* lps = sm;                     // [TT][GG] probabilities
    float* abuf = sm + TT * GG;          // [2][264], alpha stored at slot s+2
    __shared__ float redm[8];
    __shared__ float logacc_s;

    const int b = blockIdx.x;
    const int tid = threadIdx.x;
    const int wid = tid >> 5, lane = tid & 31;
    const int s = tid;
    const int ilen = ilens[b];

    // Stage probabilities
    const float* src = g_p + (size_t)g_base[b] * GG;
    for (int i = tid; i < ilen * GG; i += 256) lps[i] = src[i];

    // Per-state metadata
    int g = 0;
    float allowf = 0.f;
    if (s < SS && (s & 1)) {
        int l = s >> 1;
        g = 1 + l;
        int yr = ys[b * LL + l];
        int y = yr < 0 ? 0 : yr;
        int ypr = -1;
        if (l > 0) {
            int yp = ys[b * LL + l - 1];
            ypr = yp < 0 ? 0 : yp;
        }
        allowf = ((y != 0) && (y != ypr)) ? 1.f : 0.f;
    }

    float* a0 = abuf;        // [264]
    float* a1 = abuf + 264;
    // init: pad slots 0,1 zero in both buffers; alpha0 at slots s+2
    if (tid < 2) { a0[tid] = 0.f; a1[tid] = 0.f; }
    if (tid == 0) logacc_s = 0.f;
    __syncthreads();   // lps[0..GG) ready not guaranteed yet? staging loop covers all; need barrier after staging too
    // (staging barrier folded into this one: staging writes by all threads happen before)
    a0[s + 2] = (s == 0) ? lps[0] : ((s == 1) ? lps[1] : 0.f);
    __syncthreads();

    for (int t = 1; t < ilen; t++) {
        float nv = 0.f;
        if (s < SS)
            nv = (a0[s + 2] + a0[s + 1] + allowf * a0[s]) * lps[t * GG + g];
        // periodic rescale (uniform branch)
        if ((t & 3) == 0) {
            float m = nv;
#pragma unroll
            for (int msk = 16; msk > 0; msk >>= 1)
                m = fmaxf(m, __shfl_xor_sync(0xffffffffu, m, msk));
            if (lane == 0) redm[wid] = m;
            __syncthreads();
            float bm = redm[0];
#pragma unroll
            for (int j = 1; j < 8; j++) bm = fmaxf(bm, redm[j]);
            float inv = __fdividef(1.f, bm);
            nv *= inv;
            if (tid == 0) logacc_s += __logf(bm);
        }
        if (s < SS) a1[s + 2] = nv;
        __syncthreads();
        float* tmp = a0; a0 = a1; a1 = tmp;
    }

    if (tid == 0) {
        const int olen = olens[b];
        float va = a0[2 * olen + 2];
        float vb = a0[2 * olen + 1];
        g_ll[b] = logf(va + vb) + logacc_s;
    }
}

__global__ void finalize_kernel(float* __restrict__ out) {
    if (threadIdx.x == 0) {
        float sum = 0.0f;
        for (int i = 0; i < BSZ; i++) sum += g_ll[i];
        out[0] = -sum / (float)BSZ;
    }
}

// ---------------------------------------------------------------------------
extern "C" void kernel_launch(void* const* d_in, const int* in_sizes, int n_in,
                              void* d_out, int out_size) {
    const float* hs    = (const float*)d_in[0];
    const float* W     = (const float*)d_in[1];
    const float* bias  = (const float*)d_in[2];
    const int*   ys    = (const int*)d_in[3];
    const int*   ilens = (const int*)d_in[4];
    const int*   olens = (const int*)d_in[5];
    float* out = (float*)d_out;

    setup_convW_kernel<<<1 + BSZ + (NPAD / 32) * (EE / 32), 256>>>(ilens, ys, W);
    conv_hs_kernel<<<(MPAD * EE) / 1024, 256>>>(hs);

    const int gemm_smem = NST * 16384;   // 64 KB
    cudaFuncSetAttribute(gemm_lse_kernel,
                         cudaFuncAttributeMaxDynamicSharedMemorySize, gemm_smem);
    dim3 ggrid(NPAD / BN, MPAD / BM);    // 32 x 63
    gemm_lse_kernel<<<ggrid, 256, gemm_smem>>>(bias);

    combine_kernel<<<MM, 128>>>();                               // launch 4 (profiled)

    const int dp_smem = (TT * GG + 2 * 264) * sizeof(float);
    cudaFuncSetAttribute(ctc_dp_kernel,
                         cudaFuncAttributeMaxDynamicSharedMemorySize, dp_smem);
    ctc_dp_kernel<<<BSZ, 256, dp_smem>>>(ys, ilens, olens);

    finalize_kernel<<<1, 32>>>(out);
}